// round 5
// baseline (speedup 1.0000x reference)
#include <cuda_runtime.h>
#include <cstdint>
#include <cstddef>

#define B_   128
#define C_   2048
#define HW_  196
#define ND_  32
#define NA_  1845

#define CK     256          // floats per k-chunk (1KB per W row)
#define NCHUNK 8            // 2048 / 256
#define NBUF   3            // triple buffer, 2 stages in flight
#define ATILE  32           // answer rows per block

// Scratch for attended features (cudaMalloc is forbidden) — 1 MB.
__device__ __align__(1024) float g_att[B_ * C_];

// ---- dynamic smem layout (bytes) ----
#define SM_WSZ  (NBUF * ATILE * CK * 4)   // 98304
#define SM_XSZ  (NBUF * 4 * CK * 4)       // 12288
#define SM_W    0
#define SM_X    (SM_W + SM_WSZ)
#define SM_LIST (SM_X + SM_XSZ)           // int[128]
#define SM_BJ   (SM_LIST + 128 * 4)       // int[4]
#define SM_CNT  (SM_BJ + 16)
#define SM_IS64 (SM_CNT + 4)
#define SM_BAR  (SM_IS64 + 4)             // 3 x 8B mbarriers (8-aligned)
#define SM_TOT  (SM_BAR + 24)             // ~108.6 KB -> 2 blocks/SM

#define STAGE_BYTES (ATILE * CK * 4 + 4 * CK * 4)   // 36864

// ---------------------------------------------------------------------------
// Kernel 1: attended[b][c] = (1/196) * sum_hw mask[b][hw] * features[b][c][hw]
// One warp per (b,c) row; near HBM roofline — unchanged.
// ---------------------------------------------------------------------------
__global__ void __launch_bounds__(256) k_attend(const float* __restrict__ mask,
                                                const float* __restrict__ feat)
{
    int gw   = (blockIdx.x * 256 + threadIdx.x) >> 5;
    int lane = threadIdx.x & 31;
    if (gw >= B_ * C_) return;
    int b = gw >> 11;

    const float4* f  = (const float4*)(feat + (size_t)gw * HW_);
    const float4* mk = (const float4*)(mask + (size_t)b  * HW_);

    float4 a0 = f[lane], m0 = mk[lane];
    float s = a0.x * m0.x + a0.y * m0.y + a0.z * m0.z + a0.w * m0.w;
    if (lane < 17) {
        float4 a1 = f[lane + 32], m1 = mk[lane + 32];
        s += a1.x * m1.x + a1.y * m1.y + a1.z * m1.z + a1.w * m1.w;
    }
    #pragma unroll
    for (int o = 16; o; o >>= 1) s += __shfl_xor_sync(0xffffffffu, s, o);
    if (lane == 0) g_att[gw] = s * (1.0f / 196.0f);
}

// ---------------------------------------------------------------------------
// Helpers
// ---------------------------------------------------------------------------
__device__ __forceinline__ void fma2(unsigned long long& d,
                                     unsigned long long a,
                                     unsigned long long b)
{
    asm("fma.rn.f32x2 %0, %1, %2, %0;" : "+l"(d) : "l"(a), "l"(b));
}

__device__ __forceinline__ uint32_t smem_u32(const void* p) {
    uint32_t a;
    asm("{ .reg .u64 t; cvta.to.shared.u64 t, %1; cvt.u32.u64 %0, t; }"
        : "=r"(a) : "l"(p));
    return a;
}

__device__ __forceinline__ void mbar_init(uint32_t mbar, uint32_t cnt) {
    asm volatile("mbarrier.init.shared.b64 [%0], %1;" :: "r"(mbar), "r"(cnt)
                 : "memory");
}

__device__ __forceinline__ void mbar_wait(uint32_t mbar, uint32_t parity) {
    asm volatile(
        "{\n\t"
        ".reg .pred P;\n\t"
        "WL%=:\n\t"
        "mbarrier.try_wait.parity.acquire.cta.shared::cta.b64 P, [%0], %1, 0x989680;\n\t"
        "@P bra WD%=;\n\t"
        "bra WL%=;\n\t"
        "WD%=:\n\t"
        "}"
        :: "r"(mbar), "r"(parity) : "memory");
}

// 1KB bulk async copy gmem->smem with transaction-count completion.
__device__ __forceinline__ void bulk1k(uint32_t sdst, const void* g,
                                       uint32_t mbar)
{
    asm volatile(
        "cp.async.bulk.shared::cluster.global.mbarrier::complete_tx::bytes "
        "[%0], [%1], %2, [%3];"
        :: "r"(sdst), "l"(g), "r"(1024u), "r"(mbar) : "memory");
}

// ---------------------------------------------------------------------------
// Issue one k-chunk stage (thread 0 only): expect_tx + 32 W-row copies +
// 4 X-row copies. W rows: 1KB contiguous, 8KB gmem stride.
// ---------------------------------------------------------------------------
__device__ __forceinline__ void issue_stage(uint32_t smb,
                                            const float* __restrict__ W,
                                            size_t wrow0, int k0, int s,
                                            const int* bj)
{
    int buf = s % NBUF;
    uint32_t mbar = smb + SM_BAR + buf * 8;
    asm volatile("mbarrier.arrive.expect_tx.shared.b64 _, [%0], %1;"
                 :: "r"(mbar), "r"((uint32_t)STAGE_BYTES) : "memory");

    uint32_t wdst = smb + SM_W + buf * (ATILE * CK * 4);
    const char* gsrc = (const char*)(W + wrow0 + k0);
    #pragma unroll
    for (int r = 0; r < ATILE; r++)
        bulk1k(wdst + r * 1024, gsrc + (size_t)r * (C_ * 4), mbar);

    uint32_t xdst = smb + SM_X + buf * (4 * CK * 4);
    #pragma unroll
    for (int j = 0; j < 4; j++)
        bulk1k(xdst + j * 1024,
               (const char*)(g_att + (size_t)bj[j] * C_ + k0), mbar);
}

// ---------------------------------------------------------------------------
// One full pass over C for one (<=4)-sample group. Stage cursor s0 runs
// across passes so buf rotation/parity stay consistent (buf=s%3,
// parity=(s/3)&1). bj[] is registers only (R3 lesson).
// ---------------------------------------------------------------------------
template <int MB>
__device__ __forceinline__ void run_pass(uint32_t smb, char* sm,
                                         const float* __restrict__ W,
                                         size_t wrow0, int tid, int lane,
                                         int w4, const int* bj,
                                         int a0c, int a0nom, int d, int s0,
                                         const float* __restrict__ bias,
                                         float* __restrict__ out)
{
    unsigned long long acc[4][MB];
    #pragma unroll
    for (int r = 0; r < 4; r++)
        #pragma unroll
        for (int j = 0; j < MB; j++) acc[r][j] = 0ull;

    if (tid == 0) {
        issue_stage(smb, W, wrow0, 0,  s0,     bj);
        issue_stage(smb, W, wrow0, CK, s0 + 1, bj);
    }

    for (int k = 0; k < NCHUNK; k++) {
        int s = s0 + k;
        int buf = s % NBUF;
        mbar_wait(smb + SM_BAR + buf * 8, (s / NBUF) & 1);

        const float* Wb = (const float*)(sm + SM_W + buf * (ATILE * CK * 4));
        const float* Xb = (const float*)(sm + SM_X + buf * (4 * CK * 4));
        #pragma unroll
        for (int st = 0; st < 2; st++) {         // CK/4 = 64 float4, 2 lane-steps
            int c = lane + st * 32;
            ulonglong2 w[4];
            #pragma unroll
            for (int r = 0; r < 4; r++)
                w[r] = ((const ulonglong2*)(Wb + (w4 + r) * CK))[c];
            #pragma unroll
            for (int j = 0; j < MB; j++) {
                ulonglong2 x = ((const ulonglong2*)(Xb + j * CK))[c];
                #pragma unroll
                for (int r = 0; r < 4; r++) {
                    fma2(acc[r][j], w[r].x, x.x);
                    fma2(acc[r][j], w[r].y, x.y);
                }
            }
        }
        __syncthreads();                         // all reads of buf done (WAR)
        if (k + 2 < NCHUNK && tid == 0)
            issue_stage(smb, W, wrow0, (k + 2) * CK, s + 2, bj);
    }

    #pragma unroll
    for (int r = 0; r < 4; r++) {
        int a = a0c + w4 + r;
        #pragma unroll
        for (int j = 0; j < MB; j++) {
            float v = __uint_as_float((unsigned)(acc[r][j] & 0xffffffffu))
                    + __uint_as_float((unsigned)(acc[r][j] >> 32));
            #pragma unroll
            for (int o = 16; o; o >>= 1) v += __shfl_xor_sync(0xffffffffu, v, o);
            if (lane == 0 && a >= a0nom)         // skip clamp-duplicated rows
                out[(size_t)bj[j] * NA_ + a] = v + bias[(size_t)d * NA_ + a];
        }
    }
}

// ---------------------------------------------------------------------------
// Kernel 2: grouped GEMM, bulk-async staged. Grid (58, 32), 256 threads.
// ---------------------------------------------------------------------------
__global__ void __launch_bounds__(256, 2) k_gemm(const void* __restrict__ inst_raw,
                                                 const float* __restrict__ W,
                                                 const float* __restrict__ bias,
                                                 float* __restrict__ out)
{
    extern __shared__ char sm[];
    uint32_t smb = smem_u32(sm);
    int* s_list = (int*)(sm + SM_LIST);
    int* s_bj   = (int*)(sm + SM_BJ);
    int* s_cnt  = (int*)(sm + SM_CNT);
    int* s_is64 = (int*)(sm + SM_IS64);

    if (threadIdx.x == 0) {
        // Detect int64 vs int32 instance layout (values 0..31 => odd words 0).
        const unsigned* pw = (const unsigned*)inst_raw;
        unsigned orv = 0;
        for (int i = 1; i < 128; i += 2) orv |= pw[i];
        *s_is64 = (orv == 0) ? 1 : 0;
        *s_cnt  = 0;
        #pragma unroll
        for (int b = 0; b < NBUF; b++) mbar_init(smb + SM_BAR + b * 8, 1);
    }
    __syncthreads();

    int d = blockIdx.y;
    if (threadIdx.x < B_) {
        int v = *s_is64 ? (int)((const long long*)inst_raw)[threadIdx.x]
                        : ((const int*)inst_raw)[threadIdx.x];
        if (v == d) {
            int p = atomicAdd(s_cnt, 1);
            s_list[p] = threadIdx.x;
        }
    }
    __syncthreads();

    int m = *s_cnt;
    if (m == 0) return;                          // unused descriptor: no W read

    int tid  = threadIdx.x;
    int lane = tid & 31;
    int w4   = (tid >> 5) * 4;                   // warp's 4 rows within the tile
    int a0nom = blockIdx.x * ATILE;
    int a0c   = a0nom > NA_ - ATILE ? NA_ - ATILE : a0nom;
    size_t wrow0 = ((size_t)d * NA_ + a0c) * C_;

    int s0 = 0;                                  // global stage cursor
    for (int base = 0; base < m; base += 4) {
        int mb = m - base; if (mb > 4) mb = 4;
        if (tid < 4) s_bj[tid] = s_list[base + (tid < mb ? tid : mb - 1)];
        __syncthreads();                         // publishes s_bj; fences prior bufs

        int bj[4];                               // registers only (R3 lesson)
        #pragma unroll
        for (int j = 0; j < 4; j++) bj[j] = s_bj[j];

        switch (mb) {
            case 1:  run_pass<1>(smb, sm, W, wrow0, tid, lane, w4, bj,
                                 a0c, a0nom, d, s0, bias, out); break;
            case 2:  run_pass<2>(smb, sm, W, wrow0, tid, lane, w4, bj,
                                 a0c, a0nom, d, s0, bias, out); break;
            case 3:  run_pass<3>(smb, sm, W, wrow0, tid, lane, w4, bj,
                                 a0c, a0nom, d, s0, bias, out); break;
            default: run_pass<4>(smb, sm, W, wrow0, tid, lane, w4, bj,
                                 a0c, a0nom, d, s0, bias, out); break;
        }
        s0 += NCHUNK;
    }
}

// ---------------------------------------------------------------------------
// Inputs (metadata order): mask f32[128,1,14,14], features f32[128,2048,14,14],
// instance int[128], W f32[32,1845,2048], b f32[32,1845]. Output f32[128,1845].
// ---------------------------------------------------------------------------
extern "C" void kernel_launch(void* const* d_in, const int* in_sizes, int n_in,
                              void* d_out, int out_size)
{
    const float* mask = (const float*)d_in[0];
    const float* feat = (const float*)d_in[1];
    const void*  inst = d_in[2];
    const float* W    = (const float*)d_in[3];
    const float* bias = (const float*)d_in[4];
    float* out = (float*)d_out;

    int blocks1 = (B_ * C_) / 8;                 // warp per (b,c) row
    k_attend<<<blocks1, 256>>>(mask, feat);

    cudaFuncSetAttribute(k_gemm, cudaFuncAttributeMaxDynamicSharedMemorySize,
                         SM_TOT);
    dim3 g2((NA_ + ATILE - 1) / ATILE, ND_);     // (58, 32)
    k_gemm<<<g2, 256, SM_TOT>>>(inst, W, bias, out);
}

// round 6
// speedup vs baseline: 1.0653x; 1.0653x over previous
#include <cuda_runtime.h>
#include <cstdint>
#include <cstddef>

#define B_   128
#define C_   2048
#define HW_  196
#define ND_  32
#define NA_  1845

#define THREADS 128         // 4 warps
#define RPW     8           // answer rows per warp
#define CK      256         // floats per k-chunk (1KB per W row)
#define NCHUNK  8           // 2048 / 256
#define NBUF    2           // double buffer -> 74KB smem -> 3 blocks/SM
#define ATILE   32          // answer rows per block (4 warps x 8 rows)

// Scratch for attended features (cudaMalloc is forbidden) — 1 MB.
__device__ __align__(1024) float g_att[B_ * C_];

// ---- dynamic smem layout (bytes) ----
#define SM_WBUF (ATILE * CK * 4)          // 32768 per buf
#define SM_XBUF (4 * CK * 4)              // 4096 per buf
#define SM_W    0
#define SM_X    (SM_W + NBUF * SM_WBUF)   // 65536
#define SM_LIST (SM_X + NBUF * SM_XBUF)   // 73728, int[128]
#define SM_BJ   (SM_LIST + 128 * 4)
#define SM_CNT  (SM_BJ + 16)
#define SM_IS64 (SM_CNT + 4)
#define SM_TOT  (SM_IS64 + 4)             // ~74.3KB -> 3 blocks/SM

// ---------------------------------------------------------------------------
// Kernel 1: attended[b][c] = (1/196) * sum_hw mask[b][hw] * features[b][c][hw]
// One warp per (b,c) row; ~78% of HBM peak — unchanged.
// ---------------------------------------------------------------------------
__global__ void __launch_bounds__(256) k_attend(const float* __restrict__ mask,
                                                const float* __restrict__ feat)
{
    int gw   = (blockIdx.x * 256 + threadIdx.x) >> 5;
    int lane = threadIdx.x & 31;
    if (gw >= B_ * C_) return;
    int b = gw >> 11;

    const float4* f  = (const float4*)(feat + (size_t)gw * HW_);
    const float4* mk = (const float4*)(mask + (size_t)b  * HW_);

    float4 a0 = f[lane], m0 = mk[lane];
    float s = a0.x * m0.x + a0.y * m0.y + a0.z * m0.z + a0.w * m0.w;
    if (lane < 17) {
        float4 a1 = f[lane + 32], m1 = mk[lane + 32];
        s += a1.x * m1.x + a1.y * m1.y + a1.z * m1.z + a1.w * m1.w;
    }
    #pragma unroll
    for (int o = 16; o; o >>= 1) s += __shfl_xor_sync(0xffffffffu, s, o);
    if (lane == 0) g_att[gw] = s * (1.0f / 196.0f);
}

// ---------------------------------------------------------------------------
// Helpers
// ---------------------------------------------------------------------------
__device__ __forceinline__ void fma2(unsigned long long& d,
                                     unsigned long long a,
                                     unsigned long long b)
{
    asm("fma.rn.f32x2 %0, %1, %2, %0;" : "+l"(d) : "l"(a), "l"(b));
}

__device__ __forceinline__ uint32_t smem_u32(const void* p) {
    uint32_t a;
    asm("{ .reg .u64 t; cvta.to.shared.u64 t, %1; cvt.u32.u64 %0, t; }"
        : "=r"(a) : "l"(p));
    return a;
}

__device__ __forceinline__ void cp16(uint32_t saddr, const void* gaddr) {
    asm volatile("cp.async.cg.shared.global [%0], [%1], 16;"
                 :: "r"(saddr), "l"(gaddr));
}
__device__ __forceinline__ void cp_commit() {
    asm volatile("cp.async.commit_group;");
}
template <int N>
__device__ __forceinline__ void cp_wait() {
    asm volatile("cp.async.wait_group %0;" :: "n"(N));
}

// ---------------------------------------------------------------------------
// Issue one k-chunk stage with 128 threads.
// W: 32 rows x 64 float4 = 2048 chunks -> 16 per thread (row stride 2).
// X: 4 rows x 64 float4 = 256 chunks  -> 2 per thread (row stride 2).
// Thread t covers rows {(t>>6) + 2i}, col (t&63).
// ---------------------------------------------------------------------------
__device__ __forceinline__ void issue_stage(uint32_t smb,
                                            const float* __restrict__ W,
                                            size_t wrow0, int k0, int buf,
                                            int tid,
                                            const float* xg0,
                                            const float* xg1)
{
    int hi  = tid >> 6;                              // 0 or 1
    int col = tid & 63;

    uint32_t wdst = smb + SM_W + buf * SM_WBUF + hi * 1024 + col * 16;
    const float* gw = W + wrow0 + (size_t)hi * C_ + k0 + col * 4;
    #pragma unroll
    for (int i = 0; i < 16; i++)                     // row = hi + 2i
        cp16(wdst + i * 2048, gw + (size_t)(2 * i) * C_);

    uint32_t xdst = smb + SM_X + buf * SM_XBUF + hi * 1024 + col * 16;
    cp16(xdst,        xg0 + k0 + col * 4);           // row hi
    cp16(xdst + 2048, xg1 + k0 + col * 4);           // row hi+2
    cp_commit();
}

// ---------------------------------------------------------------------------
// One full pass over C for one (<=4)-sample group: double-buffered cp.async.
// Each warp owns 8 answer rows x MB samples. bj[] registers only (R3 lesson).
// ---------------------------------------------------------------------------
template <int MB>
__device__ __forceinline__ void run_pass(uint32_t smb, char* sm,
                                         const float* __restrict__ W,
                                         size_t wrow0, int tid, int lane,
                                         int w8, const int* bj,
                                         const float* xg0, const float* xg1,
                                         int a0c, int a0nom, int d,
                                         const float* __restrict__ bias,
                                         float* __restrict__ out)
{
    unsigned long long acc[RPW][MB];
    #pragma unroll
    for (int r = 0; r < RPW; r++)
        #pragma unroll
        for (int j = 0; j < MB; j++) acc[r][j] = 0ull;

    issue_stage(smb, W, wrow0, 0, 0, tid, xg0, xg1);

    for (int k = 0; k < NCHUNK; k++) {
        int buf = k & 1;
        if (k + 1 < NCHUNK) {
            // buf (k+1)&1 was last read at stage k-1; its trailing barrier
            // already passed, so overwriting is safe.
            issue_stage(smb, W, wrow0, (k + 1) * CK, (k + 1) & 1, tid, xg0, xg1);
            cp_wait<1>();
        } else {
            cp_wait<0>();
        }
        __syncthreads();                             // stage k visible to all

        const float* Wb = (const float*)(sm + SM_W + buf * SM_WBUF);
        const float* Xb = (const float*)(sm + SM_X + buf * SM_XBUF);
        #pragma unroll
        for (int st = 0; st < 2; st++) {             // CK/4 = 64 float4
            int c = lane + st * 32;
            ulonglong2 w[RPW];
            #pragma unroll
            for (int r = 0; r < RPW; r++)
                w[r] = ((const ulonglong2*)(Wb + (w8 + r) * CK))[c];
            #pragma unroll
            for (int j = 0; j < MB; j++) {
                ulonglong2 x = ((const ulonglong2*)(Xb + j * CK))[c];
                #pragma unroll
                for (int r = 0; r < RPW; r++) {
                    fma2(acc[r][j], w[r].x, x.x);
                    fma2(acc[r][j], w[r].y, x.y);
                }
            }
        }
        __syncthreads();                             // reads of buf done (WAR)
    }

    #pragma unroll
    for (int r = 0; r < RPW; r++) {
        int a = a0c + w8 + r;
        #pragma unroll
        for (int j = 0; j < MB; j++) {
            float v = __uint_as_float((unsigned)(acc[r][j] & 0xffffffffu))
                    + __uint_as_float((unsigned)(acc[r][j] >> 32));
            #pragma unroll
            for (int o = 16; o; o >>= 1) v += __shfl_xor_sync(0xffffffffu, v, o);
            if (lane == 0 && a >= a0nom)             // skip clamp-duplicated rows
                out[(size_t)bj[j] * NA_ + a] = v + bias[(size_t)d * NA_ + a];
        }
    }
}

// ---------------------------------------------------------------------------
// Kernel 2: grouped GEMM, cp.async double-buffered. Grid (58,32) x 128 thr.
// ---------------------------------------------------------------------------
__global__ void __launch_bounds__(THREADS, 3) k_gemm(const void* __restrict__ inst_raw,
                                                     const float* __restrict__ W,
                                                     const float* __restrict__ bias,
                                                     float* __restrict__ out)
{
    extern __shared__ char sm[];
    uint32_t smb = smem_u32(sm);
    int* s_list = (int*)(sm + SM_LIST);
    int* s_bj   = (int*)(sm + SM_BJ);
    int* s_cnt  = (int*)(sm + SM_CNT);
    int* s_is64 = (int*)(sm + SM_IS64);

    if (threadIdx.x == 0) {
        // Detect int64 vs int32 instance layout (values 0..31 => odd words 0).
        const unsigned* pw = (const unsigned*)inst_raw;
        unsigned orv = 0;
        for (int i = 1; i < 128; i += 2) orv |= pw[i];
        *s_is64 = (orv == 0) ? 1 : 0;
        *s_cnt  = 0;
    }
    __syncthreads();

    int d = blockIdx.y;
    {   // 128 threads scan all 128 instances
        int v = *s_is64 ? (int)((const long long*)inst_raw)[threadIdx.x]
                        : ((const int*)inst_raw)[threadIdx.x];
        if (v == d) {
            int p = atomicAdd(s_cnt, 1);
            s_list[p] = threadIdx.x;
        }
    }
    __syncthreads();

    int m = *s_cnt;
    if (m == 0) return;                              // unused descriptor

    int tid  = threadIdx.x;
    int lane = tid & 31;
    int w8   = (tid >> 5) * RPW;                     // warp's 8 rows in tile
    int a0nom = blockIdx.x * ATILE;
    int a0c   = a0nom > NA_ - ATILE ? NA_ - ATILE : a0nom;
    size_t wrow0 = ((size_t)d * NA_ + a0c) * C_;

    for (int base = 0; base < m; base += 4) {
        int mb = m - base; if (mb > 4) mb = 4;
        if (tid < 4) s_bj[tid] = s_list[base + (tid < mb ? tid : mb - 1)];
        __syncthreads();                             // publishes s_bj

        int bj[4];                                   // registers only
        #pragma unroll
        for (int j = 0; j < 4; j++) bj[j] = s_bj[j];
        // X staging rows for this thread: hi=(tid>>6) and hi+2.
        int hi = tid >> 6;
        const float* xg0 = g_att + (size_t)(hi ? bj[1] : bj[0]) * C_;
        const float* xg1 = g_att + (size_t)(hi ? bj[3] : bj[2]) * C_;

        switch (mb) {
            case 1:  run_pass<1>(smb, sm, W, wrow0, tid, lane, w8, bj, xg0, xg1,
                                 a0c, a0nom, d, bias, out); break;
            case 2:  run_pass<2>(smb, sm, W, wrow0, tid, lane, w8, bj, xg0, xg1,
                                 a0c, a0nom, d, bias, out); break;
            case 3:  run_pass<3>(smb, sm, W, wrow0, tid, lane, w8, bj, xg0, xg1,
                                 a0c, a0nom, d, bias, out); break;
            default: run_pass<4>(smb, sm, W, wrow0, tid, lane, w8, bj, xg0, xg1,
                                 a0c, a0nom, d, bias, out); break;
        }
    }
}

// ---------------------------------------------------------------------------
// Inputs (metadata order): mask f32[128,1,14,14], features f32[128,2048,14,14],
// instance int[128], W f32[32,1845,2048], b f32[32,1845]. Output f32[128,1845].
// ---------------------------------------------------------------------------
extern "C" void kernel_launch(void* const* d_in, const int* in_sizes, int n_in,
                              void* d_out, int out_size)
{
    const float* mask = (const float*)d_in[0];
    const float* feat = (const float*)d_in[1];
    const void*  inst = d_in[2];
    const float* W    = (const float*)d_in[3];
    const float* bias = (const float*)d_in[4];
    float* out = (float*)d_out;

    int blocks1 = (B_ * C_) / 8;                     // warp per (b,c) row
    k_attend<<<blocks1, 256>>>(mask, feat);

    cudaFuncSetAttribute(k_gemm, cudaFuncAttributeMaxDynamicSharedMemorySize,
                         SM_TOT);
    dim3 g2((NA_ + ATILE - 1) / ATILE, ND_);         // (58, 32)
    k_gemm<<<g2, THREADS, SM_TOT>>>(inst, W, bias, out);
}

// round 7
// speedup vs baseline: 1.1105x; 1.0424x over previous
#include <cuda_runtime.h>
#include <cstdint>
#include <cstddef>

#define B_   128
#define C_   2048
#define HW_  196
#define ND_  32
#define NA_  1845

#define THREADS 128         // 4 warps
#define CK      256         // floats per k-chunk (1KB per W row)
#define NCHUNK  8           // 2048 / 256
#define NBUF    2           // double buffer
#define ATILE   32          // answer rows per block

// Scratch for attended features (cudaMalloc is forbidden) — 1 MB.
__device__ __align__(1024) float g_att[B_ * C_];

// ---- dynamic smem layout (bytes) ----
// W bufs at 0 (<= 2x32KB); X bufs follow W bufs (template-dependent offset,
// always <= 72KB end). Control block lives at the fixed 72KB mark.
#define SM_LIST 73728                     // int[128]
#define SM_BJ   (SM_LIST + 128 * 4)       // int[16]
#define SM_CNT  (SM_BJ + 64)
#define SM_IS64 (SM_CNT + 4)
#define SM_TOT  (SM_IS64 + 4)             // ~74.4KB -> 3 blocks/SM (223KB/228KB)

// ---------------------------------------------------------------------------
// Kernel 1: attended[b][c] = (1/196) * sum_hw mask[b][hw] * features[b][c][hw]
// One warp per (b,c) row; ~78% of HBM peak — unchanged.
// ---------------------------------------------------------------------------
__global__ void __launch_bounds__(256) k_attend(const float* __restrict__ mask,
                                                const float* __restrict__ feat)
{
    int gw   = (blockIdx.x * 256 + threadIdx.x) >> 5;
    int lane = threadIdx.x & 31;
    if (gw >= B_ * C_) return;
    int b = gw >> 11;

    const float4* f  = (const float4*)(feat + (size_t)gw * HW_);
    const float4* mk = (const float4*)(mask + (size_t)b  * HW_);

    float4 a0 = f[lane], m0 = mk[lane];
    float s = a0.x * m0.x + a0.y * m0.y + a0.z * m0.z + a0.w * m0.w;
    if (lane < 17) {
        float4 a1 = f[lane + 32], m1 = mk[lane + 32];
        s += a1.x * m1.x + a1.y * m1.y + a1.z * m1.z + a1.w * m1.w;
    }
    #pragma unroll
    for (int o = 16; o; o >>= 1) s += __shfl_xor_sync(0xffffffffu, s, o);
    if (lane == 0) g_att[gw] = s * (1.0f / 196.0f);
}

// ---------------------------------------------------------------------------
// Helpers
// ---------------------------------------------------------------------------
__device__ __forceinline__ void fma2(unsigned long long& d,
                                     unsigned long long a,
                                     unsigned long long b)
{
    asm("fma.rn.f32x2 %0, %1, %2, %0;" : "+l"(d) : "l"(a), "l"(b));
}

__device__ __forceinline__ uint32_t smem_u32(const void* p) {
    uint32_t a;
    asm("{ .reg .u64 t; cvta.to.shared.u64 t, %1; cvt.u32.u64 %0, t; }"
        : "=r"(a) : "l"(p));
    return a;
}

__device__ __forceinline__ void cp16(uint32_t saddr, const void* gaddr) {
    asm volatile("cp.async.cg.shared.global [%0], [%1], 16;"
                 :: "r"(saddr), "l"(gaddr));
}
__device__ __forceinline__ void cp_commit() {
    asm volatile("cp.async.commit_group;");
}
template <int N>
__device__ __forceinline__ void cp_wait() {
    asm volatile("cp.async.wait_group %0;" :: "n"(N));
}

// ---------------------------------------------------------------------------
// Stage one k-chunk: W[ROWS rows][CK] + X[MBP samples][CK] into smem buf.
// ROWS*64 and MBP*64 are multiples of 128 (ROWS>=8, MBP in {4,8,16}).
// ---------------------------------------------------------------------------
template <int ROWS, int MBP>
__device__ __forceinline__ void issue_stage(uint32_t smb, char* sm,
                                            const float* __restrict__ Wg,
                                            int k0, int buf, int tid,
                                            const int* s_bj)
{
    constexpr int WS   = ROWS * 1024;            // bytes per W buf
    constexpr int XOFF = NBUF * WS;              // X region start
    constexpr int XS   = MBP * 1024;             // bytes per X buf

    uint32_t wdst = smb + buf * WS;
    #pragma unroll
    for (int i = 0; i < ROWS * 64; i += 128) {
        int idx = i + tid;
        int row = idx >> 6, col = idx & 63;
        cp16(wdst + idx * 16, Wg + (size_t)row * C_ + k0 + col * 4);
    }

    uint32_t xdst = smb + XOFF + buf * XS;
    const int* bjs = (const int*)(sm + SM_BJ);
    #pragma unroll
    for (int i = 0; i < MBP * 64; i += 128) {
        int idx = i + tid;
        int j = idx >> 6, col = idx & 63;
        cp16(xdst + idx * 16, g_att + (size_t)bjs[j] * C_ + k0 + col * 4);
    }
    cp_commit();
}

// ---------------------------------------------------------------------------
// One sub-pass: stream W rows [0,ROWS) of Wg once, RPW rows x MBP samples per
// warp, double-buffered cp.async. a_w0 = global answer index of warp's row 0.
// ---------------------------------------------------------------------------
template <int RPW, int MBP>
__device__ __forceinline__ void run_pass(uint32_t smb, char* sm,
                                         const float* __restrict__ Wg,
                                         int tid, int lane, int warp,
                                         int a_w0, int a0nom, int d,
                                         const float* __restrict__ bias,
                                         float* __restrict__ out)
{
    constexpr int ROWS = 4 * RPW;
    constexpr int WS   = ROWS * 1024;
    constexpr int XOFF = NBUF * WS;
    constexpr int XS   = MBP * 1024;

    unsigned long long acc[RPW][MBP];
    #pragma unroll
    for (int r = 0; r < RPW; r++)
        #pragma unroll
        for (int j = 0; j < MBP; j++) acc[r][j] = 0ull;

    issue_stage<ROWS, MBP>(smb, sm, Wg, 0, 0, tid, 0);

    for (int k = 0; k < NCHUNK; k++) {
        int buf = k & 1;
        if (k + 1 < NCHUNK) {
            // buf (k+1)&1 last read at stage k-1; its trailing barrier passed.
            issue_stage<ROWS, MBP>(smb, sm, Wg, (k + 1) * CK, (k + 1) & 1,
                                   tid, 0);
            cp_wait<1>();
        } else {
            cp_wait<0>();
        }
        __syncthreads();                         // stage k visible to all

        const float* Wb = (const float*)(sm + buf * WS);
        const float* Xb = (const float*)(sm + XOFF + buf * XS);
        #pragma unroll
        for (int st = 0; st < 2; st++) {         // CK/4 = 64 float4
            int c = lane + st * 32;
            ulonglong2 w[RPW];
            #pragma unroll
            for (int r = 0; r < RPW; r++)
                w[r] = ((const ulonglong2*)(Wb + (warp * RPW + r) * CK))[c];
            #pragma unroll
            for (int j = 0; j < MBP; j++) {
                ulonglong2 x = ((const ulonglong2*)(Xb + j * CK))[c];
                #pragma unroll
                for (int r = 0; r < RPW; r++) {
                    fma2(acc[r][j], w[r].x, x.x);
                    fma2(acc[r][j], w[r].y, x.y);
                }
            }
        }
        __syncthreads();                         // reads of buf done (WAR)
    }

    const int* bjs = (const int*)(sm + SM_BJ);   // stable until next mbase
    #pragma unroll
    for (int r = 0; r < RPW; r++) {
        int a = a_w0 + r;
        #pragma unroll
        for (int j = 0; j < MBP; j++) {          // padded j: duplicate row,
            float v = __uint_as_float((unsigned)(acc[r][j] & 0xffffffffu))
                    + __uint_as_float((unsigned)(acc[r][j] >> 32));
            #pragma unroll
            for (int o = 16; o; o >>= 1) v += __shfl_xor_sync(0xffffffffu, v, o);
            if (lane == 0 && a >= a0nom)         // idempotent rewrite is fine
                out[(size_t)bjs[j] * NA_ + a] = v + bias[(size_t)d * NA_ + a];
        }
    }
}

// ---------------------------------------------------------------------------
// Kernel 2: grouped GEMM. W streamed EXACTLY once per block: answer tile is
// split into sub-passes so (rows x samples) per warp stays at 32 accumulators.
// ---------------------------------------------------------------------------
__global__ void __launch_bounds__(THREADS, 3) k_gemm(const void* __restrict__ inst_raw,
                                                     const float* __restrict__ W,
                                                     const float* __restrict__ bias,
                                                     float* __restrict__ out)
{
    extern __shared__ char sm[];
    uint32_t smb = smem_u32(sm);
    int* s_list = (int*)(sm + SM_LIST);
    int* s_bj   = (int*)(sm + SM_BJ);
    int* s_cnt  = (int*)(sm + SM_CNT);
    int* s_is64 = (int*)(sm + SM_IS64);

    if (threadIdx.x == 0) {
        // Detect int64 vs int32 instance layout (values 0..31 => odd words 0).
        const unsigned* pw = (const unsigned*)inst_raw;
        unsigned orv = 0;
        for (int i = 1; i < 128; i += 2) orv |= pw[i];
        *s_is64 = (orv == 0) ? 1 : 0;
        *s_cnt  = 0;
    }
    __syncthreads();

    int d = blockIdx.y;
    {   // 128 threads scan all 128 instances
        int v = *s_is64 ? (int)((const long long*)inst_raw)[threadIdx.x]
                        : ((const int*)inst_raw)[threadIdx.x];
        if (v == d) {
            int p = atomicAdd(s_cnt, 1);
            s_list[p] = threadIdx.x;
        }
    }
    __syncthreads();

    int m = *s_cnt;
    if (m == 0) return;                              // unused descriptor

    int tid  = threadIdx.x;
    int lane = tid & 31;
    int warp = tid >> 5;
    int a0nom = blockIdx.x * ATILE;
    int a0c   = a0nom > NA_ - ATILE ? NA_ - ATILE : a0nom;
    const float* W0 = W + ((size_t)d * NA_ + a0c) * C_;

    for (int mbase = 0; mbase < m; mbase += 16) {    // >16 samples: rare
        int mc = m - mbase; if (mc > 16) mc = 16;
        __syncthreads();                             // writeback done (s_bj)
        if (tid < 16) s_bj[tid] = s_list[mbase + (tid < mc ? tid : mc - 1)];
        __syncthreads();

        if (mc <= 4) {
            run_pass<8, 4>(smb, sm, W0, tid, lane, warp,
                           a0c + warp * 8, a0nom, d, bias, out);
        } else if (mc <= 8) {
            #pragma unroll
            for (int h = 0; h < 2; h++)
                run_pass<4, 8>(smb, sm, W0 + (size_t)(h * 16) * C_, tid, lane,
                               warp, a0c + h * 16 + warp * 4, a0nom, d,
                               bias, out);
        } else {
            #pragma unroll
            for (int h = 0; h < 4; h++)
                run_pass<2, 16>(smb, sm, W0 + (size_t)(h * 8) * C_, tid, lane,
                                warp, a0c + h * 8 + warp * 2, a0nom, d,
                                bias, out);
        }
    }
}

// ---------------------------------------------------------------------------
// Inputs (metadata order): mask f32[128,1,14,14], features f32[128,2048,14,14],
// instance int[128], W f32[32,1845,2048], b f32[32,1845]. Output f32[128,1845].
// ---------------------------------------------------------------------------
extern "C" void kernel_launch(void* const* d_in, const int* in_sizes, int n_in,
                              void* d_out, int out_size)
{
    const float* mask = (const float*)d_in[0];
    const float* feat = (const float*)d_in[1];
    const void*  inst = d_in[2];
    const float* W    = (const float*)d_in[3];
    const float* bias = (const float*)d_in[4];
    float* out = (float*)d_out;

    int blocks1 = (B_ * C_) / 8;                     // warp per (b,c) row
    k_attend<<<blocks1, 256>>>(mask, feat);

    cudaFuncSetAttribute(k_gemm, cudaFuncAttributeMaxDynamicSharedMemorySize,
                         SM_TOT);
    dim3 g2((NA_ + ATILE - 1) / ATILE, ND_);         // (58, 32)
    k_gemm<<<g2, THREADS, SM_TOT>>>(inst, W, bias, out);
}

// round 8
// speedup vs baseline: 1.1853x; 1.0674x over previous
#include <cuda_runtime.h>
#include <cstdint>
#include <cstddef>

#define B_   128
#define C_   2048
#define HW_  196
#define ND_  32
#define NA_  1845

#define THREADS 128         // 4 warps
#define CK      256         // floats per k-chunk (1KB per W row)
#define NCHUNK  8           // 2048 / 256
#define ATILE   32          // answer rows per block

// Scratch for attended features (cudaMalloc is forbidden) — 1 MB.
__device__ __align__(1024) float g_att[B_ * C_];

// ---- dynamic smem layout (bytes) ----
// Buffers live in [0, 72KB): path A = 2x32KB W + 2x4KB X; path B = 3x16KB W +
// 3x8KB X. Control block at the fixed 72KB mark.
#define SM_CTRL 73728
#define SM_LIST SM_CTRL                   // int[128]
#define SM_BJ   (SM_LIST + 512)           // int[8]
#define SM_CNT  (SM_BJ + 32)
#define SM_IS64 (SM_CNT + 4)
#define SM_TOT  (SM_IS64 + 4)             // ~74.3KB -> 3 blocks/SM

// ---------------------------------------------------------------------------
// Kernel 1: attended[b][c] = (1/196) * sum_hw mask[b][hw] * features[b][c][hw]
// One warp per (b,c) row; ~78% of HBM peak — unchanged.
// ---------------------------------------------------------------------------
__global__ void __launch_bounds__(256) k_attend(const float* __restrict__ mask,
                                                const float* __restrict__ feat)
{
    int gw   = (blockIdx.x * 256 + threadIdx.x) >> 5;
    int lane = threadIdx.x & 31;
    if (gw >= B_ * C_) return;
    int b = gw >> 11;

    const float4* f  = (const float4*)(feat + (size_t)gw * HW_);
    const float4* mk = (const float4*)(mask + (size_t)b  * HW_);

    float4 a0 = f[lane], m0 = mk[lane];
    float s = a0.x * m0.x + a0.y * m0.y + a0.z * m0.z + a0.w * m0.w;
    if (lane < 17) {
        float4 a1 = f[lane + 32], m1 = mk[lane + 32];
        s += a1.x * m1.x + a1.y * m1.y + a1.z * m1.z + a1.w * m1.w;
    }
    #pragma unroll
    for (int o = 16; o; o >>= 1) s += __shfl_xor_sync(0xffffffffu, s, o);
    if (lane == 0) g_att[gw] = s * (1.0f / 196.0f);
}

// ---------------------------------------------------------------------------
// Helpers
// ---------------------------------------------------------------------------
__device__ __forceinline__ void fma2(unsigned long long& d,
                                     unsigned long long a,
                                     unsigned long long b)
{
    asm("fma.rn.f32x2 %0, %1, %2, %0;" : "+l"(d) : "l"(a), "l"(b));
}

__device__ __forceinline__ uint32_t smem_u32(const void* p) {
    uint32_t a;
    asm("{ .reg .u64 t; cvta.to.shared.u64 t, %1; cvt.u32.u64 %0, t; }"
        : "=r"(a) : "l"(p));
    return a;
}

__device__ __forceinline__ void cp16(uint32_t saddr, const void* gaddr) {
    asm volatile("cp.async.cg.shared.global [%0], [%1], 16;"
                 :: "r"(saddr), "l"(gaddr));
}
__device__ __forceinline__ void cp_commit() {
    asm volatile("cp.async.commit_group;");
}
template <int N>
__device__ __forceinline__ void cp_wait() {
    asm volatile("cp.async.wait_group %0;" :: "n"(N));
}

// ===========================================================================
// Path A (mc<=4): ROWS=32, RPW=8, MBP=4, NBUF=2, 2 barriers/chunk (R6 shape).
// ===========================================================================
__device__ __forceinline__ void issueA(uint32_t smb,
                                       const float* __restrict__ Wg, int k0,
                                       int buf, int tid,
                                       const float* xg0, const float* xg1)
{
    int hi = tid >> 6, col = tid & 63;                 // rows {hi+2i}
    uint32_t wdst = smb + buf * 32768 + hi * 1024 + col * 16;
    const float* gw = Wg + (size_t)hi * C_ + k0 + col * 4;
    #pragma unroll
    for (int i = 0; i < 16; i++)
        cp16(wdst + i * 2048, gw + (size_t)(2 * i) * C_);

    uint32_t xdst = smb + 65536 + buf * 4096 + hi * 1024 + col * 16;
    cp16(xdst,        xg0 + k0 + col * 4);             // X row hi
    cp16(xdst + 2048, xg1 + k0 + col * 4);             // X row hi+2
    cp_commit();
}

__device__ __forceinline__ void runA(uint32_t smb, char* sm,
                                     const float* __restrict__ Wg,
                                     int tid, int lane, int warp,
                                     const int* bj,
                                     const float* xg0, const float* xg1,
                                     int a0c, int a0nom, int d,
                                     const float* __restrict__ bias,
                                     float* __restrict__ out)
{
    unsigned long long acc[8][4];
    #pragma unroll
    for (int r = 0; r < 8; r++)
        #pragma unroll
        for (int j = 0; j < 4; j++) acc[r][j] = 0ull;

    issueA(smb, Wg, 0, 0, tid, xg0, xg1);

    for (int k = 0; k < NCHUNK; k++) {
        int buf = k & 1;
        if (k + 1 < NCHUNK) {
            issueA(smb, Wg, (k + 1) * CK, (k + 1) & 1, tid, xg0, xg1);
            cp_wait<1>();
        } else {
            cp_wait<0>();
        }
        __syncthreads();

        const float* Wb = (const float*)(sm + buf * 32768);
        const float* Xb = (const float*)(sm + 65536 + buf * 4096);
        #pragma unroll
        for (int st = 0; st < 2; st++) {
            int c = lane + st * 32;
            ulonglong2 w[8];
            #pragma unroll
            for (int r = 0; r < 8; r++)
                w[r] = ((const ulonglong2*)(Wb + (warp * 8 + r) * CK))[c];
            #pragma unroll
            for (int j = 0; j < 4; j++) {
                ulonglong2 x = ((const ulonglong2*)(Xb + j * CK))[c];
                #pragma unroll
                for (int r = 0; r < 8; r++) {
                    fma2(acc[r][j], w[r].x, x.x);
                    fma2(acc[r][j], w[r].y, x.y);
                }
            }
        }
        __syncthreads();                               // WAR on buf
    }

    #pragma unroll
    for (int r = 0; r < 8; r++) {
        int a = a0c + warp * 8 + r;
        #pragma unroll
        for (int j = 0; j < 4; j++) {
            float v = __uint_as_float((unsigned)(acc[r][j] & 0xffffffffu))
                    + __uint_as_float((unsigned)(acc[r][j] >> 32));
            #pragma unroll
            for (int o = 16; o; o >>= 1) v += __shfl_xor_sync(0xffffffffu, v, o);
            if (lane == 0 && a >= a0nom)
                out[(size_t)bj[j] * NA_ + a] = v + bias[(size_t)d * NA_ + a];
        }
    }
}

// ===========================================================================
// Path B (5<=mc<=8): flattened 16-stage pipeline over (h,k). ROWS=16, RPW=4,
// MBP=8, NBUF=3, 2-stage prefetch lookahead, ONE barrier per stage.
// WAR chain: compute(s-1) -> barrier(s) -> issue(s+2) overwrites buf (s-1)%3.
// ===========================================================================
__device__ __forceinline__ void issueB(uint32_t smb, char* sm,
                                       const float* __restrict__ Wg32,
                                       int s, int tid)
{
    int h = s >> 3, k0 = (s & 7) * CK, buf = s % 3;
    const float* Wg = Wg32 + (size_t)(h * 16) * C_;

    uint32_t wdst = smb + buf * 16384;                 // 16 rows x 64 f4
    #pragma unroll
    for (int i = 0; i < 8; i++) {
        int idx = i * 128 + tid;
        int row = idx >> 6, col = idx & 63;
        cp16(wdst + idx * 16, Wg + (size_t)row * C_ + k0 + col * 4);
    }

    const int* bjs = (const int*)(sm + SM_BJ);
    uint32_t xdst = smb + 49152 + buf * 8192;          // 8 rows x 64 f4
    #pragma unroll
    for (int i = 0; i < 4; i++) {
        int idx = i * 128 + tid;
        int j = idx >> 6, col = idx & 63;
        cp16(xdst + idx * 16, g_att + (size_t)bjs[j] * C_ + k0 + col * 4);
    }
    cp_commit();
}

__device__ __forceinline__ void runB(uint32_t smb, char* sm,
                                     const float* __restrict__ Wg32,
                                     int tid, int lane, int warp,
                                     const int* bj,
                                     int a0c, int a0nom, int d,
                                     const float* __restrict__ bias,
                                     float* __restrict__ out)
{
    unsigned long long acc[4][8];
    #pragma unroll
    for (int r = 0; r < 4; r++)
        #pragma unroll
        for (int j = 0; j < 8; j++) acc[r][j] = 0ull;

    issueB(smb, sm, Wg32, 0, tid);
    issueB(smb, sm, Wg32, 1, tid);

    for (int s = 0; s < 2 * NCHUNK; s++) {
        if (s + 1 < 2 * NCHUNK) cp_wait<1>(); else cp_wait<0>();
        __syncthreads();                               // stage s visible; frees
        if (s + 2 < 2 * NCHUNK) issueB(smb, sm, Wg32, s + 2, tid);

        int buf = s % 3;
        const float* Wb = (const float*)(sm + buf * 16384);
        const float* Xb = (const float*)(sm + 49152 + buf * 8192);
        #pragma unroll
        for (int st = 0; st < 2; st++) {
            int c = lane + st * 32;
            ulonglong2 w[4];
            #pragma unroll
            for (int r = 0; r < 4; r++)
                w[r] = ((const ulonglong2*)(Wb + (warp * 4 + r) * CK))[c];
            #pragma unroll
            for (int j = 0; j < 8; j++) {
                ulonglong2 x = ((const ulonglong2*)(Xb + j * CK))[c];
                #pragma unroll
                for (int r = 0; r < 4; r++) {
                    fma2(acc[r][j], w[r].x, x.x);
                    fma2(acc[r][j], w[r].y, x.y);
                }
            }
        }

        if ((s & 7) == 7) {                            // end of sub-tile h
            int h = s >> 3;
            #pragma unroll
            for (int r = 0; r < 4; r++) {
                int a = a0c + h * 16 + warp * 4 + r;
                #pragma unroll
                for (int j = 0; j < 8; j++) {
                    float v = __uint_as_float((unsigned)(acc[r][j] & 0xffffffffu))
                            + __uint_as_float((unsigned)(acc[r][j] >> 32));
                    #pragma unroll
                    for (int o = 16; o; o >>= 1)
                        v += __shfl_xor_sync(0xffffffffu, v, o);
                    if (lane == 0 && a >= a0nom)       // padded j: idempotent
                        out[(size_t)bj[j] * NA_ + a] =
                            v + bias[(size_t)d * NA_ + a];
                    acc[r][j] = 0ull;
                }
            }
        }
    }
}

// ---------------------------------------------------------------------------
// Kernel 2: grouped GEMM. Sample groups of 8; m<=8 streams W exactly once.
// ---------------------------------------------------------------------------
__global__ void __launch_bounds__(THREADS, 3) k_gemm(const void* __restrict__ inst_raw,
                                                     const float* __restrict__ W,
                                                     const float* __restrict__ bias,
                                                     float* __restrict__ out)
{
    extern __shared__ char sm[];
    uint32_t smb = smem_u32(sm);
    int* s_list = (int*)(sm + SM_LIST);
    int* s_bj   = (int*)(sm + SM_BJ);
    int* s_cnt  = (int*)(sm + SM_CNT);
    int* s_is64 = (int*)(sm + SM_IS64);

    if (threadIdx.x == 0) {
        // Detect int64 vs int32 instance layout (values 0..31 => odd words 0).
        const unsigned* pw = (const unsigned*)inst_raw;
        unsigned orv = 0;
        for (int i = 1; i < 128; i += 2) orv |= pw[i];
        *s_is64 = (orv == 0) ? 1 : 0;
        *s_cnt  = 0;
    }
    __syncthreads();

    int d = blockIdx.y;
    {   // 128 threads scan all 128 instances
        int v = *s_is64 ? (int)((const long long*)inst_raw)[threadIdx.x]
                        : ((const int*)inst_raw)[threadIdx.x];
        if (v == d) {
            int p = atomicAdd(s_cnt, 1);
            s_list[p] = threadIdx.x;
        }
    }
    __syncthreads();

    int m = *s_cnt;
    if (m == 0) return;                                // unused descriptor

    int tid  = threadIdx.x;
    int lane = tid & 31;
    int warp = tid >> 5;
    int a0nom = blockIdx.x * ATILE;
    int a0c   = a0nom > NA_ - ATILE ? NA_ - ATILE : a0nom;
    const float* W0 = W + ((size_t)d * NA_ + a0c) * C_;

    for (int mbase = 0; mbase < m; mbase += 8) {
        int mc = m - mbase; if (mc > 8) mc = 8;
        __syncthreads();                               // prior group fully done
        if (tid < 8) s_bj[tid] = s_list[mbase + (tid < mc ? tid : mc - 1)];
        __syncthreads();

        int bj[8];                                     // registers only (R3)
        #pragma unroll
        for (int j = 0; j < 8; j++) bj[j] = s_bj[j];

        if (mc <= 4) {
            int hi = tid >> 6;
            const float* xg0 = g_att + (size_t)(hi ? bj[1] : bj[0]) * C_;
            const float* xg1 = g_att + (size_t)(hi ? bj[3] : bj[2]) * C_;
            runA(smb, sm, W0, tid, lane, warp, bj, xg0, xg1,
                 a0c, a0nom, d, bias, out);
        } else {
            runB(smb, sm, W0, tid, lane, warp, bj,
                 a0c, a0nom, d, bias, out);
        }
    }
}

// ---------------------------------------------------------------------------
// Inputs (metadata order): mask f32[128,1,14,14], features f32[128,2048,14,14],
// instance int[128], W f32[32,1845,2048], b f32[32,1845]. Output f32[128,1845].
// ---------------------------------------------------------------------------
extern "C" void kernel_launch(void* const* d_in, const int* in_sizes, int n_in,
                              void* d_out, int out_size)
{
    const float* mask = (const float*)d_in[0];
    const float* feat = (const float*)d_in[1];
    const void*  inst = d_in[2];
    const float* W    = (const float*)d_in[3];
    const float* bias = (const float*)d_in[4];
    float* out = (float*)d_out;

    int blocks1 = (B_ * C_) / 8;                       // warp per (b,c) row
    k_attend<<<blocks1, 256>>>(mask, feat);

    cudaFuncSetAttribute(k_gemm, cudaFuncAttributeMaxDynamicSharedMemorySize,
                         SM_TOT);
    dim3 g2((NA_ + ATILE - 1) / ATILE, ND_);           // (58, 32)
    k_gemm<<<g2, THREADS, SM_TOT>>>(inst, W, bias, out);
}